// round 5
// baseline (speedup 1.0000x reference)
#include <cuda_runtime.h>
#include <cuda_bf16.h>

// Fused kernel, software-pipelined, occupancy-tuned:
//  - block decodes E -> canonical Horner coefficient slots in shared
//  - linear+quadratic coefficients (30) hoisted to registers; the 35 cubic
//    coefficients stay in shared and are re-loaded (broadcast LDS) each
//    iteration. This cuts regs from 122 to <=85 -> 3 CTAs/SM (24 warps)
//    instead of 2 (16 warps), buying ~1.5x latency-hiding.
//  - prefetch next 2 rows before computing current 2 rows.

#define ROWS 2

__global__ __launch_bounds__(256, 3)
void ExternalForcesSI_main_kernel(const float4* __restrict__ x,
                                  const float* __restrict__ t,
                                  const float* __restrict__ layer,
                                  const float* __restrict__ omegas,
                                  const float* __restrict__ ef,
                                  const int*   __restrict__ E,
                                  float2* __restrict__ out,
                                  int n) {
    __shared__ float sC1[5];
    __shared__ float sC2[25];
    __shared__ float sC3[125];
    __shared__ float sTrig[10];

    // ---- block-local decode of E -> canonical coefficient slots ----
    const int tx = threadIdx.x;
    if (tx < 55) {
        int vars[3];
        int nv = 0;
        #pragma unroll
        for (int j = 0; j < 5; j++) {
            int c = E[tx * 5 + j];
            for (int r = 0; r < c; r++) vars[nv++] = j;   // ascending
        }
        float coef = layer[tx];
        if (nv == 1)      sC1[vars[0]] = coef;
        else if (nv == 2) sC2[vars[0] * 5 + vars[1]] = coef;
        else              sC3[(vars[0] * 5 + vars[1]) * 5 + vars[2]] = coef;
    }
    if (tx >= 64 && tx < 74) sTrig[tx - 64] = layer[55 + (tx - 64)];
    __syncthreads();

    // ---- hoist ONLY the small coefficient sets into registers ----
    float c1[5], c2[15], ctc[5], cts[5];
    {
        int q2 = 0;
        #pragma unroll
        for (int i = 0; i < 5; i++) {
            c1[i] = sC1[i];
            ctc[i] = sTrig[i];
            cts[i] = sTrig[5 + i];
            #pragma unroll
            for (int j = i; j < 5; j++) c2[q2++] = sC2[i * 5 + j];
        }
    }
    const float w0 = omegas[0];
    const float w1 = omegas[1];
    const float e0 = ef[0];
    const float e1 = ef[1];

    const int stride = gridDim.x * blockDim.x;   // per-row stride
    const int tid = blockIdx.x * blockDim.x + tx;

    // ---- prologue: load first batch ----
    float v[ROWS][5];
    int   idx[ROWS];
    #pragma unroll
    for (int r = 0; r < ROWS; r++) {
        idx[r] = tid + r * stride;
        bool a = idx[r] < n;
        float4 xv = a ? x[idx[r]] : make_float4(0.f, 0.f, 0.f, 0.f);
        float  tv = a ? t[idx[r]] : 0.f;
        v[r][0] = xv.x; v[r][1] = xv.y; v[r][2] = xv.z; v[r][3] = xv.w; v[r][4] = tv;
    }

    for (int i0 = tid; i0 < n; i0 += ROWS * stride) {
        // ---- prefetch next batch FIRST (LDGs in flight during compute) ----
        float vn[ROWS][5];
        int   nidx[ROWS];
        #pragma unroll
        for (int r = 0; r < ROWS; r++) {
            nidx[r] = i0 + (ROWS + r) * stride;
            bool a = nidx[r] < n;
            float4 xv = a ? x[nidx[r]] : make_float4(0.f, 0.f, 0.f, 0.f);
            float  tv = a ? t[nidx[r]] : 0.f;
            vn[r][0] = xv.x; vn[r][1] = xv.y; vn[r][2] = xv.z; vn[r][3] = xv.w; vn[r][4] = tv;
        }

        // ---- trig: 10*ROWS independent MUFUs issue early ----
        float strig[ROWS];
        #pragma unroll
        for (int r = 0; r < ROWS; r++) {
            float ta = 0.f, tb = 0.f;
            #pragma unroll
            for (int j = 0; j < 5; j++) {
                ta = fmaf(ctc[j], __cosf(w0 * v[r][j]), ta);
                tb = fmaf(cts[j], __sinf(w1 * v[r][j]), tb);
            }
            strig[r] = ta + tb;
        }

        // ---- degree-3 Horner, coefficient-major for c3:
        //      each cubic coefficient is ONE broadcast LDS feeding ROWS FMAs.
        float part[ROWS][5];
        {
            int q2 = 0;
            #pragma unroll
            for (int i = 0; i < 5; i++) {
                float ui[ROWS];
                #pragma unroll
                for (int r = 0; r < ROWS; r++) ui[r] = c1[i];
                #pragma unroll
                for (int j = i; j < 5; j++) {
                    float tij[ROWS];
                    float cq = c2[q2++];
                    #pragma unroll
                    for (int r = 0; r < ROWS; r++) tij[r] = cq;
                    #pragma unroll
                    for (int k = j; k < 5; k++) {
                        float c3v = sC3[(i * 5 + j) * 5 + k];  // broadcast LDS
                        #pragma unroll
                        for (int r = 0; r < ROWS; r++)
                            tij[r] = fmaf(v[r][k], c3v, tij[r]);
                    }
                    #pragma unroll
                    for (int r = 0; r < ROWS; r++)
                        ui[r] = fmaf(v[r][j], tij[r], ui[r]);
                }
                #pragma unroll
                for (int r = 0; r < ROWS; r++)
                    part[r][i] = v[r][i] * ui[r];
            }
        }
        #pragma unroll
        for (int r = 0; r < ROWS; r++) {
            float s = ((part[r][0] + part[r][1]) + (part[r][2] + part[r][3]))
                      + (part[r][4] + strig[r]);
            if (idx[r] < n) out[idx[r]] = make_float2(s * e0, s * e1);
        }

        // ---- rotate pipeline ----
        #pragma unroll
        for (int r = 0; r < ROWS; r++) {
            idx[r] = nidx[r];
            #pragma unroll
            for (int j = 0; j < 5; j++) v[r][j] = vn[r][j];
        }
    }
}

extern "C" void kernel_launch(void* const* d_in, const int* in_sizes, int n_in,
                              void* d_out, int out_size) {
    // metadata order: x, t, layer, omegas, ext_filter, E
    const float4* x      = (const float4*)d_in[0];
    const float*  t      = (const float*)d_in[1];
    const float*  layer  = (const float*)d_in[2];
    const float*  omegas = (const float*)d_in[3];
    const float*  ef     = (const float*)d_in[4];
    const int*    E      = (const int*)d_in[5];
    float2* out = (float2*)d_out;

    const int n = in_sizes[1];  // N_DATA (element count of t)

    // 3 CTAs/SM * 148 SMs = 444 blocks (single wave, 24 warps/SM resident).
    // ~8.8 rows/thread -> ~4.4 pipelined iterations of 2 rows.
    ExternalForcesSI_main_kernel<<<444, 256>>>(x, t, layer, omegas, ef, E, out, n);
}

// round 8
// speedup vs baseline: 1.1837x; 1.1837x over previous
#include <cuda_runtime.h>
#include <cuda_bf16.h>

// R5: back to R3's register-resident coefficients (the R4 shared-mem version
// proved LDS-in-the-loop is a loser), plus instruction-count surgery:
//  - templated exact iteration count, fully unrolled mainloop (no loop
//    overhead, rotation by register renaming)
//  - min-clamped loads (1 instr) instead of select-predicated zero fills;
//    only the final store is predicated
//  - tree-shaped trig/poly reductions, MUFUs issued right after loads

#define ROWS 2
#define NBLK 296
#define NTHR 256
#define TOTT (NBLK * NTHR)   // 75776 threads

template<int NITER>
__global__ __launch_bounds__(NTHR, 2)
void ExternalForcesSI_main_kernel(const float4* __restrict__ x,
                                  const float* __restrict__ t,
                                  const float* __restrict__ layer,
                                  const float* __restrict__ omegas,
                                  const float* __restrict__ ef,
                                  const int*   __restrict__ E,
                                  float2* __restrict__ out,
                                  int n, int iters_rt) {
    __shared__ float sC1[5];
    __shared__ float sC2[25];
    __shared__ float sC3[125];
    __shared__ float sTrig[10];

    // ---- block-local decode of E -> canonical coefficient slots ----
    const int tx = threadIdx.x;
    if (tx < 55) {
        int vars[3];
        int nv = 0;
        #pragma unroll
        for (int j = 0; j < 5; j++) {
            int c = E[tx * 5 + j];
            for (int r = 0; r < c; r++) vars[nv++] = j;   // ascending
        }
        float coef = layer[tx];
        if (nv == 1)      sC1[vars[0]] = coef;
        else if (nv == 2) sC2[vars[0] * 5 + vars[1]] = coef;
        else              sC3[(vars[0] * 5 + vars[1]) * 5 + vars[2]] = coef;
    }
    if (tx >= 64 && tx < 74) sTrig[tx - 64] = layer[55 + (tx - 64)];
    __syncthreads();

    // ---- hoist ALL coefficients into registers (broadcast LDS, once) ----
    float c1[5], c2[15], c3[35], ctc[5], cts[5];
    {
        int q2 = 0, q3 = 0;
        #pragma unroll
        for (int i = 0; i < 5; i++) {
            c1[i] = sC1[i];
            ctc[i] = sTrig[i];
            cts[i] = sTrig[5 + i];
            #pragma unroll
            for (int j = i; j < 5; j++) {
                c2[q2++] = sC2[i * 5 + j];
                #pragma unroll
                for (int k = j; k < 5; k++)
                    c3[q3++] = sC3[(i * 5 + j) * 5 + k];
            }
        }
    }
    const float w0 = omegas[0];
    const float w1 = omegas[1];
    const float e0 = ef[0];
    const float e1 = ef[1];

    const int tid = blockIdx.x * NTHR + tx;
    const int nm1 = n - 1;
    const int iters = (NITER > 0) ? NITER : iters_rt;

    // ---- prologue: clamped load of first batch ----
    float v[ROWS][5];
    #pragma unroll
    for (int r = 0; r < ROWS; r++) {
        int ci = min(tid + r * TOTT, nm1);
        float4 xv = x[ci];
        float  tv = t[ci];
        v[r][0] = xv.x; v[r][1] = xv.y; v[r][2] = xv.z; v[r][3] = xv.w; v[r][4] = tv;
    }

    #pragma unroll
    for (int it = 0; it < iters; it++) {
        const int i0 = tid + it * (ROWS * TOTT);

        // ---- prefetch next batch FIRST (clamped; LDGs fly during compute) ----
        float vn[ROWS][5];
        if (it + 1 < iters) {
            #pragma unroll
            for (int r = 0; r < ROWS; r++) {
                int ci = min(i0 + (ROWS + r) * TOTT, nm1);
                float4 xv = x[ci];
                float  tv = t[ci];
                vn[r][0] = xv.x; vn[r][1] = xv.y; vn[r][2] = xv.z;
                vn[r][3] = xv.w; vn[r][4] = tv;
            }
        }

        // ---- trig: all 10*ROWS MUFUs issue early, tree accumulation ----
        float strig[ROWS];
        #pragma unroll
        for (int r = 0; r < ROWS; r++) {
            float C[5], S[5];
            #pragma unroll
            for (int j = 0; j < 5; j++) {
                C[j] = __cosf(w0 * v[r][j]);
                S[j] = __sinf(w1 * v[r][j]);
            }
            float a01 = fmaf(ctc[0], C[0], ctc[1] * C[1]);
            float a23 = fmaf(ctc[2], C[2], ctc[3] * C[3]);
            float b01 = fmaf(cts[0], S[0], cts[1] * S[1]);
            float b23 = fmaf(cts[2], S[2], cts[3] * S[3]);
            float a4  = fmaf(ctc[4], C[4], cts[4] * S[4]);
            strig[r] = ((a01 + a23) + (b01 + b23)) + a4;
        }

        // ---- degree-3 Horner: 55 FMAs/row, 5 independent ui chains ----
        #pragma unroll
        for (int r = 0; r < ROWS; r++) {
            float part[5];
            int q2 = 0, q3 = 0;
            #pragma unroll
            for (int i = 0; i < 5; i++) {
                float ui = c1[i];
                #pragma unroll
                for (int j = i; j < 5; j++) {
                    float tij = c2[q2++];
                    #pragma unroll
                    for (int k = j; k < 5; k++)
                        tij = fmaf(v[r][k], c3[q3++], tij);
                    ui = fmaf(v[r][j], tij, ui);
                }
                part[i] = v[r][i] * ui;
            }
            float s = ((part[0] + part[1]) + (part[2] + part[3]))
                      + (part[4] + strig[r]);
            int idx = i0 + r * TOTT;
            if (idx < n) out[idx] = make_float2(s * e0, s * e1);
        }

        // ---- rotate (renamed away by the unroll) ----
        if (it + 1 < iters) {
            #pragma unroll
            for (int r = 0; r < ROWS; r++)
                #pragma unroll
                for (int j = 0; j < 5; j++) v[r][j] = vn[r][j];
        }
    }
}

extern "C" void kernel_launch(void* const* d_in, const int* in_sizes, int n_in,
                              void* d_out, int out_size) {
    // metadata order: x, t, layer, omegas, ext_filter, E
    const float4* x      = (const float4*)d_in[0];
    const float*  t      = (const float*)d_in[1];
    const float*  layer  = (const float*)d_in[2];
    const float*  omegas = (const float*)d_in[3];
    const float*  ef     = (const float*)d_in[4];
    const int*    E      = (const int*)d_in[5];
    float2* out = (float2*)d_out;

    const int n = in_sizes[1];  // N_DATA (element count of t)
    const int iters = (n + ROWS * TOTT - 1) / (ROWS * TOTT);

    if (iters == 7) {
        // N_DATA = 1M path: exact compile-time trip count, fully unrolled.
        ExternalForcesSI_main_kernel<7><<<NBLK, NTHR>>>(
            x, t, layer, omegas, ef, E, out, n, iters);
    } else {
        ExternalForcesSI_main_kernel<0><<<NBLK, NTHR>>>(
            x, t, layer, omegas, ef, E, out, n, iters);
    }
}